// round 8
// baseline (speedup 1.0000x reference)
#include <cuda_runtime.h>
#include <math.h>

// ---------------------------------------------------------------------------
// Problem constants
// ---------------------------------------------------------------------------
#define BATCH 32
#define CIN   256
#define SIDE  64
#define NTOK  1024
#define KD    256
#define SCALE 0.0625f

// GEMM tiling: 128x128 block, BK=32, 256 threads (8 warps 2x4), warp 64x32
#define BM  128
#define BN  128
#define BK  32
#define SKP 36
#define NSTAGE 3
#define STAGE_FLOATS (128 * SKP)                    // per A or B stage
#define SMEM_FLOATS (2 * NSTAGE * STAGE_FLOATS)
#define SMEM_BYTES  (SMEM_FLOATS * 4)               // 110592

#define XP 66
#define XPC (XP * XP)

// ---------------------------------------------------------------------------
// Scratch (all mma-input buffers hold tf32-rounded values)
// ---------------------------------------------------------------------------
__device__ float g_pb  [3 * NTOK * KD];
__device__ float g_wt  [3 * KD * 1024];
__device__ float g_upwt[1024 * KD];
__device__ float g_xp  [BATCH * CIN * XPC];
__device__ float g_qkv [3 * BATCH * NTOK * KD];
__device__ float g_vt  [BATCH * KD * NTOK];
__device__ float g_S   [BATCH * NTOK * NTOK];
__device__ float g_o1  [BATCH * NTOK * KD];

// ---------------------------------------------------------------------------
// Helpers
// ---------------------------------------------------------------------------
__device__ __forceinline__ float f2tf(float f) {
    unsigned u;
    asm("cvt.rna.tf32.f32 %0, %1;" : "=r"(u) : "f"(f));
    return __uint_as_float(u);
}

__device__ __forceinline__ void cp16(unsigned d, const void* s) {
    asm volatile("cp.async.cg.shared.global [%0], [%1], 16;\n" :: "r"(d), "l"(s));
}
__device__ __forceinline__ void cp8(unsigned d, const void* s) {
    asm volatile("cp.async.ca.shared.global [%0], [%1], 8;\n" :: "r"(d), "l"(s));
}
#define CP_COMMIT() asm volatile("cp.async.commit_group;\n" ::: "memory")
#define CP_WAIT1()  asm volatile("cp.async.wait_group 1;\n" ::: "memory")
#define CP_WAIT0()  asm volatile("cp.async.wait_group 0;\n" ::: "memory")

__device__ __forceinline__ float posT(int e, int p) {
    if (p <= 0) return 0.0f;
    float inv = __powf(10000.0f, -(float)(2 * (e >> 1)) / 16.0f);
    float a = (float)p * inv;
    return (e & 1) ? cosf(a) : sinf(a);
}

// ---------------------------------------------------------------------------
// Preprocessing
// ---------------------------------------------------------------------------
__global__ void pb_kernel(const float* __restrict__ qw, const float* __restrict__ qb,
                          const float* __restrict__ kw, const float* __restrict__ kb,
                          const float* __restrict__ vw, const float* __restrict__ vb) {
    int gid = blockIdx.x * 256 + threadIdx.x;
    int o = gid & 255;
    int n = (gid >> 8) & 1023;
    int t = gid >> 18;
    const float* w  = (t == 0) ? qw : (t == 1) ? kw : vw;
    const float* bb = (t == 0) ? qb : (t == 1) ? kb : vb;
    int oy = n >> 5, ox = n & 31;
    float cx = (ox > 0) ? 1.0f : 0.0f;
    float cy = (oy > 0) ? 1.0f : 0.0f;
    float acc = bb[o];
    const float* wo = w + (size_t)o * 1152;
#pragma unroll
    for (int e = 0; e < 16; e++) {
        const float* wx = wo + (256 + e) * 4;
        const float* wy = wo + (272 + e) * 4;
        acc += (wx[0] * cx + wx[1]) * posT(e, 2 * oy - 1)
             + (wx[2] * cx + wx[3]) * posT(e, 2 * oy)
             + (wy[0] * cy + wy[2]) * posT(e, 2 * ox - 1)
             + (wy[1] * cy + wy[3]) * posT(e, 2 * ox);
    }
    g_pb[gid] = acc;
}

__global__ void wt_kernel(const float* __restrict__ qw,
                          const float* __restrict__ kw,
                          const float* __restrict__ vw) {
    int gid = blockIdx.x * 256 + threadIdx.x;
    int k = gid & 1023;
    int o = (gid >> 10) & 255;
    int t = gid >> 18;
    const float* w = (t == 0) ? qw : (t == 1) ? kw : vw;
    g_wt[gid] = f2tf(w[(size_t)o * 1152 + k]);
}

__global__ void upwt_kernel(const float* __restrict__ upw) {
    int gid = blockIdx.x * 256 + threadIdx.x;
    int v = gid & 255;
    int j = gid >> 8;
    g_upwt[gid] = f2tf(upw[(size_t)(j >> 2) * 1024 + v * 4 + (j & 3)]);
}

__global__ void xpad_kernel(const float* __restrict__ x) {
    long long gid = (long long)blockIdx.x * 256 + threadIdx.x;
    if (gid >= (long long)BATCH * CIN * XPC) return;
    int cp = gid % XP;
    int rp = (gid / XP) % XP;
    long long bc = gid / XPC;
    float v = 0.0f;
    if (rp >= 1 && rp <= SIDE && cp >= 1 && cp <= SIDE)
        v = x[bc * (SIDE * SIDE) + (size_t)(rp - 1) * SIDE + (cp - 1)];
    g_xp[gid] = f2tf(v);
}

__global__ void vt_kernel() {
    __shared__ float tile[32][33];
    int b = blockIdx.z;
    int m0 = blockIdx.x * 32, v0 = blockIdx.y * 32;
    const float* V = g_qkv + ((size_t)2 * BATCH + b) * NTOK * KD;
    float* Vt = g_vt + (size_t)b * KD * NTOK;
    int tx = threadIdx.x, ty = threadIdx.y;
#pragma unroll
    for (int i = 0; i < 32; i += 8)
        tile[ty + i][tx] = V[(size_t)(m0 + ty + i) * KD + v0 + tx];
    __syncthreads();
#pragma unroll
    for (int i = 0; i < 32; i += 8)
        Vt[(size_t)(v0 + ty + i) * NTOK + m0 + tx] = tile[tx][ty + i];
}

// ---------------------------------------------------------------------------
// Async row staging: 128 rows x 32 k
// ---------------------------------------------------------------------------
__device__ __forceinline__ void stage_rows(float* dst, const float* src, int ld, int tid) {
#pragma unroll
    for (int i = 0; i < 4; i++) {
        int f4 = tid + 256 * i;
        int r = f4 >> 3, c = (f4 & 7) * 4;
        unsigned d = (unsigned)__cvta_generic_to_shared(dst + r * SKP + c);
        cp16(d, src + (size_t)r * ld + c);
    }
}

// ---------------------------------------------------------------------------
// Warp mma over one BK=32 slab (warp tile 64x32)
// ---------------------------------------------------------------------------
__device__ __forceinline__ void mma_slab(const float* As, const float* Bs,
                                         float acc[4][4][4],
                                         int m_off, int n_off, int qid, int tig) {
#pragma unroll
    for (int k8 = 0; k8 < 4; k8++) {
        int k0 = k8 * 8;
        unsigned a[4][4], bfr[4][2];
#pragma unroll
        for (int mf = 0; mf < 4; mf++) {
            int r = m_off + mf * 16 + qid;
            a[mf][0] = __float_as_uint(As[r * SKP + k0 + tig]);
            a[mf][1] = __float_as_uint(As[(r + 8) * SKP + k0 + tig]);
            a[mf][2] = __float_as_uint(As[r * SKP + k0 + tig + 4]);
            a[mf][3] = __float_as_uint(As[(r + 8) * SKP + k0 + tig + 4]);
        }
#pragma unroll
        for (int nf = 0; nf < 4; nf++) {
            int c = n_off + nf * 8 + qid;
            bfr[nf][0] = __float_as_uint(Bs[c * SKP + k0 + tig]);
            bfr[nf][1] = __float_as_uint(Bs[c * SKP + k0 + tig + 4]);
        }
#pragma unroll
        for (int mf = 0; mf < 4; mf++)
#pragma unroll
            for (int nf = 0; nf < 4; nf++)
                asm volatile(
                    "mma.sync.aligned.m16n8k8.row.col.f32.tf32.tf32.f32 "
                    "{%0,%1,%2,%3}, {%4,%5,%6,%7}, {%8,%9}, {%0,%1,%2,%3};"
                    : "+f"(acc[mf][nf][0]), "+f"(acc[mf][nf][1]),
                      "+f"(acc[mf][nf][2]), "+f"(acc[mf][nf][3])
                    : "r"(a[mf][0]), "r"(a[mf][1]), "r"(a[mf][2]), "r"(a[mf][3]),
                      "r"(bfr[nf][0]), "r"(bfr[nf][1]));
    }
}

#define GEMM_PREAMBLE()                                                        \
    extern __shared__ float sm[];                                              \
    float* Abuf[NSTAGE]; float* Bbuf[NSTAGE];                                  \
    _Pragma("unroll")                                                          \
    for (int st_ = 0; st_ < NSTAGE; st_++) {                                   \
        Abuf[st_] = sm + (2 * st_) * STAGE_FLOATS;                             \
        Bbuf[st_] = sm + (2 * st_ + 1) * STAGE_FLOATS;                         \
    }                                                                          \
    int tid = threadIdx.x;                                                     \
    int lane = tid & 31, wid = tid >> 5;                                       \
    int qid = lane >> 2, tig = lane & 3;                                       \
    int m_off = (wid >> 2) * 64, n_off = (wid & 3) * 32;                       \
    float acc[4][4][4] = {};

// 3-stage circular pipeline, ONE __syncthreads per slab.
// iter s: wait for group s; sync (frees buf (s-1)%3 = (s+2)%3); issue s+2; mma s.
#define PIPE_LOOP(NS, STAGE_S)                                                 \
    STAGE_S(0, 0);                                                             \
    CP_COMMIT();                                                               \
    if ((NS) > 1) { STAGE_S(1, 1); CP_COMMIT(); }                              \
    for (int s = 0; s < (NS); s++) {                                           \
        if (s + 1 < (NS)) { CP_WAIT1(); } else { CP_WAIT0(); }                 \
        __syncthreads();                                                       \
        if (s + 2 < (NS)) {                                                    \
            STAGE_S((s + 2) % NSTAGE, s + 2);                                  \
            CP_COMMIT();                                                       \
        }                                                                      \
        mma_slab(Abuf[s % NSTAGE], Bbuf[s % NSTAGE], acc, m_off, n_off, qid, tig); \
    }

// ---------------------------------------------------------------------------
// G1: projection GEMM, ReLU(acc+pb) -> g_qkv. grid (8 nt, 2 ot, 3*B)
// ---------------------------------------------------------------------------
__global__ __launch_bounds__(256) void proj_kernel() {
    GEMM_PREAMBLE();
    int b = blockIdx.z / 3, t = blockIdx.z % 3;
    int n0 = blockIdx.x * BM, o0 = blockIdx.y * BN;

    int n_l = tid & 127;
    int ch0 = tid >> 7;
    int n = n0 + n_l, oy = n >> 5, ox = n & 31;
    const float* xpb = g_xp + ((size_t)(b * CIN + ch0) * XP + 2 * oy) * XP + 2 * ox;
    unsigned sA[NSTAGE];
#pragma unroll
    for (int st = 0; st < NSTAGE; st++)
        sA[st] = (unsigned)__cvta_generic_to_shared(Abuf[st] + n_l * SKP + ch0 * 4);
    const float* Wb = g_wt + (size_t)(t * 256 + o0) * 1024;

#define PROJ_STAGE(bi, s)                                                      \
    do {                                                                       \
        _Pragma("unroll")                                                      \
        for (int i_ = 0; i_ < 4; i_++) {                                       \
            const float* p_ = xpb + (size_t)(8 * (s) + 2 * i_) * XPC;          \
            unsigned d_ = sA[bi] + (unsigned)(i_ * 8) * 4;                     \
            cp8(d_, p_);                                                       \
            cp8(d_ + 8, p_ + XP);                                              \
        }                                                                      \
        stage_rows(Bbuf[bi], Wb + (s) * 32, 1024, tid);                        \
    } while (0)

    PIPE_LOOP(32, PROJ_STAGE);

    const float* pbp = g_pb + (size_t)t * NTOK * KD;
    float* outp = g_qkv + ((size_t)t * BATCH + b) * NTOK * KD;
#pragma unroll
    for (int mf = 0; mf < 4; mf++)
#pragma unroll
        for (int nf = 0; nf < 4; nf++) {
            int r = n0 + m_off + mf * 16 + qid;
            int c = o0 + n_off + nf * 8 + 2 * tig;
            float2 p0 = *(const float2*)&pbp[(size_t)r * KD + c];
            float2 p1 = *(const float2*)&pbp[(size_t)(r + 8) * KD + c];
            float2 r0, r1;
            r0.x = f2tf(fmaxf(acc[mf][nf][0] + p0.x, 0.0f));
            r0.y = f2tf(fmaxf(acc[mf][nf][1] + p0.y, 0.0f));
            r1.x = f2tf(fmaxf(acc[mf][nf][2] + p1.x, 0.0f));
            r1.y = f2tf(fmaxf(acc[mf][nf][3] + p1.y, 0.0f));
            *(float2*)&outp[(size_t)r * KD + c] = r0;
            *(float2*)&outp[(size_t)(r + 8) * KD + c] = r1;
        }
}

// ---------------------------------------------------------------------------
// G2: scores, lower-triangular tiles. grid (8 nt, 8 mt, B)
// ---------------------------------------------------------------------------
__global__ __launch_bounds__(256) void score_kernel() {
    int nt = blockIdx.x, mt = blockIdx.y, b = blockIdx.z;
    if (mt > nt) return;
    GEMM_PREAMBLE();
    const float* Q  = g_qkv + (size_t)b * NTOK * KD + (size_t)nt * BM * KD;
    const float* Km = g_qkv + ((size_t)BATCH + b) * NTOK * KD + (size_t)mt * BN * KD;

#define SCORE_STAGE(bi, s)                                                     \
    do {                                                                       \
        stage_rows(Abuf[bi], Q + (s) * 32, KD, tid);                           \
        stage_rows(Bbuf[bi], Km + (s) * 32, KD, tid);                          \
    } while (0)

    PIPE_LOOP(8, SCORE_STAGE);

    float* Sp = g_S + (size_t)b * NTOK * NTOK;
    int n0 = nt * BM, m0 = mt * BN;
#pragma unroll
    for (int mf = 0; mf < 4; mf++)
#pragma unroll
        for (int nf = 0; nf < 4; nf++) {
            int r = n0 + m_off + mf * 16 + qid;
            int c = m0 + n_off + nf * 8 + 2 * tig;
            float2 r0, r1;
            r0.x = acc[mf][nf][0] * SCALE; r0.y = acc[mf][nf][1] * SCALE;
            r1.x = acc[mf][nf][2] * SCALE; r1.y = acc[mf][nf][3] * SCALE;
            *(float2*)&Sp[(size_t)r * NTOK + c] = r0;
            *(float2*)&Sp[(size_t)(r + 8) * NTOK + c] = r1;
        }
}

// ---------------------------------------------------------------------------
// Softmax; writes tf32-rounded probs
// ---------------------------------------------------------------------------
__global__ __launch_bounds__(128) void softmax_kernel() {
    int bid = blockIdx.x;
    int n = bid & 1023;
    float* row = g_S + (size_t)bid * NTOK;
    int L = n + 1;
    int Lpad = ((n >> 7) + 1) << 7;
    __shared__ float buf[1024];
    __shared__ float red[4];
    int tid = threadIdx.x;

    float mx = -1e30f;
    for (int m = tid; m < L; m += 128) { float v = row[m]; buf[m] = v; mx = fmaxf(mx, v); }
#pragma unroll
    for (int off = 16; off; off >>= 1) mx = fmaxf(mx, __shfl_xor_sync(~0u, mx, off));
    if ((tid & 31) == 0) red[tid >> 5] = mx;
    __syncthreads();
    mx = fmaxf(fmaxf(red[0], red[1]), fmaxf(red[2], red[3]));

    float s = 0.0f;
    for (int m = tid; m < L; m += 128) { float e = __expf(buf[m] - mx); buf[m] = e; s += e; }
#pragma unroll
    for (int off = 16; off; off >>= 1) s += __shfl_xor_sync(~0u, s, off);
    __syncthreads();
    if ((tid & 31) == 0) red[tid >> 5] = s;
    __syncthreads();
    s = red[0] + red[1] + red[2] + red[3];
    float inv = 1.0f / s;

    for (int m = tid; m < Lpad; m += 128)
        row[m] = (m < L) ? f2tf(buf[m] * inv) : 0.0f;
}

// ---------------------------------------------------------------------------
// G3: out1 = probs @ V. grid (8 nt, 2 vt, B)
// ---------------------------------------------------------------------------
__global__ __launch_bounds__(256) void av_kernel() {
    GEMM_PREAMBLE();
    int nt = blockIdx.x, vt = blockIdx.y, b = blockIdx.z;
    const float* P  = g_S + (size_t)b * NTOK * NTOK + (size_t)nt * BM * NTOK;
    const float* Vt = g_vt + (size_t)b * KD * NTOK + (size_t)vt * BN * NTOK;
    int ns = (nt + 1) * 4;

#define AV_STAGE(bi, s)                                                        \
    do {                                                                       \
        stage_rows(Abuf[bi], P + (s) * 32, NTOK, tid);                         \
        stage_rows(Bbuf[bi], Vt + (s) * 32, NTOK, tid);                        \
    } while (0)

    PIPE_LOOP(ns, AV_STAGE);

    float* Op = g_o1 + (size_t)b * NTOK * KD;
    int n0 = nt * BM, v0 = vt * BN;
#pragma unroll
    for (int mf = 0; mf < 4; mf++)
#pragma unroll
        for (int nf = 0; nf < 4; nf++) {
            int r = n0 + m_off + mf * 16 + qid;
            int c = v0 + n_off + nf * 8 + 2 * tig;
            float2 r0 = make_float2(f2tf(acc[mf][nf][0]), f2tf(acc[mf][nf][1]));
            float2 r1 = make_float2(f2tf(acc[mf][nf][2]), f2tf(acc[mf][nf][3]));
            *(float2*)&Op[(size_t)r * KD + c] = r0;
            *(float2*)&Op[(size_t)(r + 8) * KD + c] = r1;
        }
}

// ---------------------------------------------------------------------------
// G4: convT GEMM + fused residual scatter. grid (8 nt, 8 jt, B)
// ---------------------------------------------------------------------------
__global__ __launch_bounds__(256) void up_kernel(const float* __restrict__ xin,
                                                 const float* __restrict__ upb,
                                                 float* __restrict__ out) {
    GEMM_PREAMBLE();
    int nt = blockIdx.x, jt = blockIdx.y, b = blockIdx.z;
    int n0 = nt * BM, j0 = jt * BN;
    const float* A = g_o1 + (size_t)b * NTOK * KD + (size_t)n0 * KD;
    const float* Bw = g_upwt + (size_t)j0 * KD;

#define UP_STAGE(bi, s)                                                        \
    do {                                                                       \
        stage_rows(Abuf[bi], A + (s) * 32, KD, tid);                           \
        stage_rows(Bbuf[bi], Bw + (s) * 32, KD, tid);                          \
    } while (0)

    PIPE_LOOP(8, UP_STAGE);

    __syncthreads();                                  // all reads of sm done
    float* Cs = sm;                                   // 128*130 floats
#pragma unroll
    for (int mf = 0; mf < 4; mf++)
#pragma unroll
        for (int nf = 0; nf < 4; nf++) {
            int rl = m_off + mf * 16 + qid;
            int cl = n_off + nf * 8 + 2 * tig;
            *(float2*)&Cs[rl * 130 + cl] = make_float2(acc[mf][nf][0], acc[mf][nf][1]);
            *(float2*)&Cs[(rl + 8) * 130 + cl] = make_float2(acc[mf][nf][2], acc[mf][nf][3]);
        }
    __syncthreads();

#pragma unroll
    for (int it = 0; it < 64; it++) {
        int e = it * 256 + tid;
        int c   = e & 63;
        int r_l = (e >> 6) & 7;
        int o_l = e >> 9;
        int jl = o_l * 4 + (r_l & 1) * 2 + (c & 1);
        int nl = (r_l >> 1) * 32 + (c >> 1);
        int o = jt * 32 + o_l;
        size_t gi = (((size_t)b * CIN + o) * SIDE + nt * 8 + r_l) * SIDE + c;
        out[gi] = xin[gi] + upb[o] + Cs[nl * 130 + jl];
    }
}

// ---------------------------------------------------------------------------
// Launch
// ---------------------------------------------------------------------------
extern "C" void kernel_launch(void* const* d_in, const int* in_sizes, int n_in,
                              void* d_out, int out_size) {
    const float* x   = (const float*)d_in[0];
    const float* q_w = (const float*)d_in[1];
    const float* q_b = (const float*)d_in[2];
    const float* k_w = (const float*)d_in[3];
    const float* k_b = (const float*)d_in[4];
    const float* v_w = (const float*)d_in[5];
    const float* v_b = (const float*)d_in[6];
    const float* up_w = (const float*)d_in[7];
    const float* up_b = (const float*)d_in[8];
    float* out = (float*)d_out;

    static bool attr_done = false;
    if (!attr_done) {
        cudaFuncSetAttribute(proj_kernel,  cudaFuncAttributeMaxDynamicSharedMemorySize, SMEM_BYTES);
        cudaFuncSetAttribute(score_kernel, cudaFuncAttributeMaxDynamicSharedMemorySize, SMEM_BYTES);
        cudaFuncSetAttribute(av_kernel,    cudaFuncAttributeMaxDynamicSharedMemorySize, SMEM_BYTES);
        cudaFuncSetAttribute(up_kernel,    cudaFuncAttributeMaxDynamicSharedMemorySize, SMEM_BYTES);
        attr_done = true;
    }

    long long xp_total = (long long)BATCH * CIN * XPC;
    xpad_kernel<<<(unsigned)((xp_total + 255) / 256), 256>>>(x);
    pb_kernel<<<3 * NTOK * KD / 256, 256>>>(q_w, q_b, k_w, k_b, v_w, v_b);
    wt_kernel<<<3 * 256 * 1024 / 256, 256>>>(q_w, k_w, v_w);
    upwt_kernel<<<1024 * KD / 256, 256>>>(up_w);
    proj_kernel<<<dim3(8, 2, BATCH * 3), 256, SMEM_BYTES>>>();
    vt_kernel<<<dim3(32, 8, BATCH), dim3(32, 8)>>>();
    score_kernel<<<dim3(8, 8, BATCH), 256, SMEM_BYTES>>>();
    softmax_kernel<<<BATCH * NTOK, 128>>>();
    av_kernel<<<dim3(8, 2, BATCH), 256, SMEM_BYTES>>>();
    up_kernel<<<dim3(8, 8, BATCH), 256, SMEM_BYTES>>>(x, up_b, out);
}

// round 9
// speedup vs baseline: 1.3179x; 1.3179x over previous
#include <cuda_runtime.h>
#include <cuda_fp16.h>
#include <math.h>

// ---------------------------------------------------------------------------
// Problem constants
// ---------------------------------------------------------------------------
#define BATCH 32
#define CIN   256
#define SIDE  64
#define NTOK  1024
#define KD    256
#define SCALE 0.0625f

// GEMM tiling: 128x128 block, BK=32 (halves), 256 threads (8 warps 2x4)
#define BM  128
#define BN  128
#define SKPH 40                                   // smem row stride in halves
#define STAGE_HALVES (128 * SKPH)                 // 5120 halves = 10240 B
#define SMEM_BYTES 66560                          // max(4*10240, Cs 128*130*4)

#define XP 66
#define XPC (XP * XP)

// ---------------------------------------------------------------------------
// Scratch (all mma inputs stored as fp16)
// ---------------------------------------------------------------------------
__device__ float  g_pb  [3 * NTOK * KD];          // pos+bias fp32
__device__ __half g_wt  [3 * KD * 1024];          // proj weights [t][o][k]
__device__ __half g_upwt[1024 * KD];              // up weights [j][v]
__device__ __half g_xp  [BATCH * CIN * XPC];      // zero-padded x
__device__ __half g_qkv [3 * BATCH * NTOK * KD];  // Q/K/V [t][b][n][o]
__device__ __half g_vt  [BATCH * KD * NTOK];      // V transposed [b][v][m]
__device__ float  g_S   [BATCH * NTOK * NTOK];    // scores fp32
__device__ __half g_P   [BATCH * NTOK * NTOK];    // probs fp16
__device__ __half g_o1  [BATCH * NTOK * KD];      // attn @ V [b][n][v]

// ---------------------------------------------------------------------------
// Helpers
// ---------------------------------------------------------------------------
__device__ __forceinline__ void cp16(unsigned d, const void* s) {
    asm volatile("cp.async.cg.shared.global [%0], [%1], 16;\n" :: "r"(d), "l"(s));
}
__device__ __forceinline__ void cp4(unsigned d, const void* s) {
    asm volatile("cp.async.ca.shared.global [%0], [%1], 4;\n" :: "r"(d), "l"(s));
}
#define CP_COMMIT() asm volatile("cp.async.commit_group;\n" ::: "memory")
#define CP_WAIT1()  asm volatile("cp.async.wait_group 1;\n" ::: "memory")
#define CP_WAIT0()  asm volatile("cp.async.wait_group 0;\n" ::: "memory")

__device__ __forceinline__ float posT(int e, int p) {
    if (p <= 0) return 0.0f;
    float inv = __powf(10000.0f, -(float)(2 * (e >> 1)) / 16.0f);
    float a = (float)p * inv;
    return (e & 1) ? cosf(a) : sinf(a);
}

// ---------------------------------------------------------------------------
// Preprocessing
// ---------------------------------------------------------------------------
__global__ void pb_kernel(const float* __restrict__ qw, const float* __restrict__ qb,
                          const float* __restrict__ kw, const float* __restrict__ kb,
                          const float* __restrict__ vw, const float* __restrict__ vb) {
    int gid = blockIdx.x * 256 + threadIdx.x;
    int o = gid & 255;
    int n = (gid >> 8) & 1023;
    int t = gid >> 18;
    const float* w  = (t == 0) ? qw : (t == 1) ? kw : vw;
    const float* bb = (t == 0) ? qb : (t == 1) ? kb : vb;
    int oy = n >> 5, ox = n & 31;
    float cx = (ox > 0) ? 1.0f : 0.0f;
    float cy = (oy > 0) ? 1.0f : 0.0f;
    float acc = bb[o];
    const float* wo = w + (size_t)o * 1152;
#pragma unroll
    for (int e = 0; e < 16; e++) {
        const float* wx = wo + (256 + e) * 4;
        const float* wy = wo + (272 + e) * 4;
        acc += (wx[0] * cx + wx[1]) * posT(e, 2 * oy - 1)
             + (wx[2] * cx + wx[3]) * posT(e, 2 * oy)
             + (wy[0] * cy + wy[2]) * posT(e, 2 * ox - 1)
             + (wy[1] * cy + wy[3]) * posT(e, 2 * ox);
    }
    g_pb[gid] = acc;
}

__global__ void wt_kernel(const float* __restrict__ qw,
                          const float* __restrict__ kw,
                          const float* __restrict__ vw) {
    int gid = blockIdx.x * 256 + threadIdx.x;     // (t*256 + o)*1024 + k
    int k = gid & 1023;
    int o = (gid >> 10) & 255;
    int t = gid >> 18;
    const float* w = (t == 0) ? qw : (t == 1) ? kw : vw;
    g_wt[gid] = __float2half_rn(w[(size_t)o * 1152 + k]);
}

__global__ void upwt_kernel(const float* __restrict__ upw) {
    int gid = blockIdx.x * 256 + threadIdx.x;     // j*256 + v
    int v = gid & 255;
    int j = gid >> 8;
    g_upwt[gid] = __float2half_rn(upw[(size_t)(j >> 2) * 1024 + v * 4 + (j & 3)]);
}

__global__ void xpad_kernel(const float* __restrict__ x) {
    long long gid = (long long)blockIdx.x * 256 + threadIdx.x;
    if (gid >= (long long)BATCH * CIN * XPC) return;
    int cp = gid % XP;
    int rp = (gid / XP) % XP;
    long long bc = gid / XPC;
    float v = 0.0f;
    if (rp >= 1 && rp <= SIDE && cp >= 1 && cp <= SIDE)
        v = x[bc * (SIDE * SIDE) + (size_t)(rp - 1) * SIDE + (cp - 1)];
    g_xp[gid] = __float2half_rn(v);
}

// g_vt[b][v][m] = V[b][m][v]
__global__ void vt_kernel() {
    __shared__ __half tile[32][34];
    int b = blockIdx.z;
    int m0 = blockIdx.x * 32, v0 = blockIdx.y * 32;
    const __half* V = g_qkv + ((size_t)2 * BATCH + b) * NTOK * KD;
    __half* Vt = g_vt + (size_t)b * KD * NTOK;
    int tx = threadIdx.x, ty = threadIdx.y;
#pragma unroll
    for (int i = 0; i < 32; i += 8)
        tile[ty + i][tx] = V[(size_t)(m0 + ty + i) * KD + v0 + tx];
    __syncthreads();
#pragma unroll
    for (int i = 0; i < 32; i += 8)
        Vt[(size_t)(v0 + ty + i) * NTOK + m0 + tx] = tile[tx][ty + i];
}

// ---------------------------------------------------------------------------
// Async staging: 128 rows x 32 halves (64 B/row = 4 x 16B chunks)
// ---------------------------------------------------------------------------
__device__ __forceinline__ void stage_rows_h(__half* dst, const __half* src,
                                             int ld, int tid) {
#pragma unroll
    for (int i = 0; i < 2; i++) {
        int f = tid + 256 * i;
        int r = f >> 2, sg = (f & 3) * 8;          // 8-half (16B) segment
        unsigned d = (unsigned)__cvta_generic_to_shared(dst + r * SKPH + sg);
        cp16(d, src + (size_t)r * ld + sg);
    }
}

// ---------------------------------------------------------------------------
// Warp mma over one BK=32 slab: 2 x m16n8k16 k-steps, warp tile 64x32
// ---------------------------------------------------------------------------
__device__ __forceinline__ void mma_slab(const __half* As, const __half* Bs,
                                         float acc[4][4][4],
                                         int m_off, int n_off, int qid, int tig) {
#pragma unroll
    for (int kk = 0; kk < 2; kk++) {
        int k0 = kk * 16;
        unsigned a[4][4], bf[4][2];
#pragma unroll
        for (int mf = 0; mf < 4; mf++) {
            int r = m_off + mf * 16 + qid;
            a[mf][0] = *(const unsigned*)&As[r * SKPH + k0 + 2 * tig];
            a[mf][1] = *(const unsigned*)&As[(r + 8) * SKPH + k0 + 2 * tig];
            a[mf][2] = *(const unsigned*)&As[r * SKPH + k0 + 8 + 2 * tig];
            a[mf][3] = *(const unsigned*)&As[(r + 8) * SKPH + k0 + 8 + 2 * tig];
        }
#pragma unroll
        for (int nf = 0; nf < 4; nf++) {
            int c = n_off + nf * 8 + qid;
            bf[nf][0] = *(const unsigned*)&Bs[c * SKPH + k0 + 2 * tig];
            bf[nf][1] = *(const unsigned*)&Bs[c * SKPH + k0 + 8 + 2 * tig];
        }
#pragma unroll
        for (int mf = 0; mf < 4; mf++)
#pragma unroll
            for (int nf = 0; nf < 4; nf++)
                asm volatile(
                    "mma.sync.aligned.m16n8k16.row.col.f32.f16.f16.f32 "
                    "{%0,%1,%2,%3}, {%4,%5,%6,%7}, {%8,%9}, {%0,%1,%2,%3};"
                    : "+f"(acc[mf][nf][0]), "+f"(acc[mf][nf][1]),
                      "+f"(acc[mf][nf][2]), "+f"(acc[mf][nf][3])
                    : "r"(a[mf][0]), "r"(a[mf][1]), "r"(a[mf][2]), "r"(a[mf][3]),
                      "r"(bf[nf][0]), "r"(bf[nf][1]));
    }
}

#define GEMM_PREAMBLE()                                                        \
    extern __shared__ __half smh[];                                            \
    __half* Abuf[2] = {smh, smh + 2 * STAGE_HALVES};                           \
    __half* Bbuf[2] = {smh + STAGE_HALVES, smh + 3 * STAGE_HALVES};            \
    int tid = threadIdx.x;                                                     \
    int lane = tid & 31, wid = tid >> 5;                                       \
    int qid = lane >> 2, tig = lane & 3;                                       \
    int m_off = (wid >> 2) * 64, n_off = (wid & 3) * 32;                       \
    float acc[4][4][4] = {};

// R7-style 2-stage pipeline (empirically best)
#define PIPE_LOOP(NS, STAGE_S)                                                 \
    STAGE_S(0, 0);                                                             \
    CP_COMMIT();                                                               \
    for (int s = 0; s < (NS); s++) {                                           \
        int p = s & 1;                                                         \
        if (s + 1 < (NS)) {                                                    \
            STAGE_S(1 - p, s + 1);                                             \
            CP_COMMIT();                                                       \
            CP_WAIT1();                                                        \
        } else {                                                               \
            CP_WAIT0();                                                        \
        }                                                                      \
        __syncthreads();                                                       \
        mma_slab(Abuf[p], Bbuf[p], acc, m_off, n_off, qid, tig);               \
        __syncthreads();                                                       \
    }

// ---------------------------------------------------------------------------
// G1: projection GEMM, ReLU(acc+pb) -> g_qkv (fp16). grid (8 nt, 2 ot, 3*B)
// ---------------------------------------------------------------------------
__global__ __launch_bounds__(256) void proj_kernel() {
    GEMM_PREAMBLE();
    int b = blockIdx.z / 3, t = blockIdx.z % 3;
    int n0 = blockIdx.x * BM, o0 = blockIdx.y * BN;

    // thread owns token n_l; channel slots j = ch0 + 2i within slab (8 ch/slab)
    int n_l = tid & 127;
    int ch0 = tid >> 7;                            // 0/1
    int n = n0 + n_l, oy = n >> 5, ox = n & 31;
    const __half* xpb = g_xp + ((size_t)(b * CIN + ch0) * XP + 2 * oy) * XP + 2 * ox;
    unsigned sA[2];
#pragma unroll
    for (int st = 0; st < 2; st++)
        sA[st] = (unsigned)__cvta_generic_to_shared(Abuf[st] + n_l * SKPH + 4 * ch0);
    const __half* Wb = g_wt + (size_t)(t * 256 + o0) * 1024;

    // per channel slot: halves {4j,4j+1} = padded row 2oy cols 2ox..+1,
    //                   halves {4j+2,4j+3} = padded row 2oy+1 (src + XP)
#define PROJ_STAGE(bi, s)                                                      \
    do {                                                                       \
        _Pragma("unroll")                                                      \
        for (int i_ = 0; i_ < 4; i_++) {                                       \
            const __half* p_ = xpb + (size_t)(8 * (s) + 2 * i_) * XPC;         \
            unsigned d_ = sA[bi] + (unsigned)(i_ * 16);                        \
            cp4(d_, p_);                                                       \
            cp4(d_ + 4, p_ + XP);                                              \
        }                                                                      \
        stage_rows_h(Bbuf[bi], Wb + (s) * 32, 1024, tid);                      \
    } while (0)

    PIPE_LOOP(32, PROJ_STAGE);

    const float* pbp = g_pb + (size_t)t * NTOK * KD;
    __half* outp = g_qkv + ((size_t)t * BATCH + b) * NTOK * KD;
#pragma unroll
    for (int mf = 0; mf < 4; mf++)
#pragma unroll
        for (int nf = 0; nf < 4; nf++) {
            int r = n0 + m_off + mf * 16 + qid;
            int c = o0 + n_off + nf * 8 + 2 * tig;
            float2 p0 = *(const float2*)&pbp[(size_t)r * KD + c];
            float2 p1 = *(const float2*)&pbp[(size_t)(r + 8) * KD + c];
            __half2 h0, h1;
            h0.x = __float2half_rn(fmaxf(acc[mf][nf][0] + p0.x, 0.0f));
            h0.y = __float2half_rn(fmaxf(acc[mf][nf][1] + p0.y, 0.0f));
            h1.x = __float2half_rn(fmaxf(acc[mf][nf][2] + p1.x, 0.0f));
            h1.y = __float2half_rn(fmaxf(acc[mf][nf][3] + p1.y, 0.0f));
            *(__half2*)&outp[(size_t)r * KD + c] = h0;
            *(__half2*)&outp[(size_t)(r + 8) * KD + c] = h1;
        }
}

// ---------------------------------------------------------------------------
// G2: scores fp32, lower-triangular tiles. grid (8 nt, 8 mt, B)
// ---------------------------------------------------------------------------
__global__ __launch_bounds__(256) void score_kernel() {
    int nt = blockIdx.x, mt = blockIdx.y, b = blockIdx.z;
    if (mt > nt) return;
    GEMM_PREAMBLE();
    const __half* Q  = g_qkv + (size_t)b * NTOK * KD + (size_t)nt * BM * KD;
    const __half* Km = g_qkv + ((size_t)BATCH + b) * NTOK * KD + (size_t)mt * BN * KD;

#define SCORE_STAGE(bi, s)                                                     \
    do {                                                                       \
        stage_rows_h(Abuf[bi], Q + (s) * 32, KD, tid);                         \
        stage_rows_h(Bbuf[bi], Km + (s) * 32, KD, tid);                        \
    } while (0)

    PIPE_LOOP(8, SCORE_STAGE);

    float* Sp = g_S + (size_t)b * NTOK * NTOK;
    int n0 = nt * BM, m0 = mt * BN;
#pragma unroll
    for (int mf = 0; mf < 4; mf++)
#pragma unroll
        for (int nf = 0; nf < 4; nf++) {
            int r = n0 + m_off + mf * 16 + qid;
            int c = m0 + n_off + nf * 8 + 2 * tig;
            float2 r0, r1;
            r0.x = acc[mf][nf][0] * SCALE; r0.y = acc[mf][nf][1] * SCALE;
            r1.x = acc[mf][nf][2] * SCALE; r1.y = acc[mf][nf][3] * SCALE;
            *(float2*)&Sp[(size_t)r * NTOK + c] = r0;
            *(float2*)&Sp[(size_t)(r + 8) * NTOK + c] = r1;
        }
}

// ---------------------------------------------------------------------------
// Softmax: reads fp32 S, writes fp16 probs to g_P (zero-padded to 128)
// ---------------------------------------------------------------------------
__global__ __launch_bounds__(128) void softmax_kernel() {
    int bid = blockIdx.x;
    int n = bid & 1023;
    const float* row = g_S + (size_t)bid * NTOK;
    __half* prow = g_P + (size_t)bid * NTOK;
    int L = n + 1;
    int Lpad = ((n >> 7) + 1) << 7;
    __shared__ float buf[1024];
    __shared__ float red[4];
    int tid = threadIdx.x;

    float mx = -1e30f;
    for (int m = tid; m < L; m += 128) { float v = row[m]; buf[m] = v; mx = fmaxf(mx, v); }
#pragma unroll
    for (int off = 16; off; off >>= 1) mx = fmaxf(mx, __shfl_xor_sync(~0u, mx, off));
    if ((tid & 31) == 0) red[tid >> 5] = mx;
    __syncthreads();
    mx = fmaxf(fmaxf(red[0], red[1]), fmaxf(red[2], red[3]));

    float s = 0.0f;
    for (int m = tid; m < L; m += 128) { float e = __expf(buf[m] - mx); buf[m] = e; s += e; }
#pragma unroll
    for (int off = 16; off; off >>= 1) s += __shfl_xor_sync(~0u, s, off);
    __syncthreads();
    if ((tid & 31) == 0) red[tid >> 5] = s;
    __syncthreads();
    s = red[0] + red[1] + red[2] + red[3];
    float inv = 1.0f / s;

    for (int m = tid; m < Lpad; m += 128)
        prow[m] = (m < L) ? __float2half_rn(buf[m] * inv) : __half(0.0f);
}

// ---------------------------------------------------------------------------
// G3: out1 = probs @ V. grid (8 nt, 2 vt, B)
// ---------------------------------------------------------------------------
__global__ __launch_bounds__(256) void av_kernel() {
    GEMM_PREAMBLE();
    int nt = blockIdx.x, vt = blockIdx.y, b = blockIdx.z;
    const __half* P  = g_P + (size_t)b * NTOK * NTOK + (size_t)nt * BM * NTOK;
    const __half* Vt = g_vt + (size_t)b * KD * NTOK + (size_t)vt * BN * NTOK;
    int ns = (nt + 1) * 4;

#define AV_STAGE(bi, s)                                                        \
    do {                                                                       \
        stage_rows_h(Abuf[bi], P + (s) * 32, NTOK, tid);                       \
        stage_rows_h(Bbuf[bi], Vt + (s) * 32, NTOK, tid);                      \
    } while (0)

    PIPE_LOOP(ns, AV_STAGE);

    __half* Op = g_o1 + (size_t)b * NTOK * KD;
    int n0 = nt * BM, v0 = vt * BN;
#pragma unroll
    for (int mf = 0; mf < 4; mf++)
#pragma unroll
        for (int nf = 0; nf < 4; nf++) {
            int r = n0 + m_off + mf * 16 + qid;
            int c = v0 + n_off + nf * 8 + 2 * tig;
            __half2 h0, h1;
            h0.x = __float2half_rn(acc[mf][nf][0]);
            h0.y = __float2half_rn(acc[mf][nf][1]);
            h1.x = __float2half_rn(acc[mf][nf][2]);
            h1.y = __float2half_rn(acc[mf][nf][3]);
            *(__half2*)&Op[(size_t)r * KD + c] = h0;
            *(__half2*)&Op[(size_t)(r + 8) * KD + c] = h1;
        }
}

// ---------------------------------------------------------------------------
// G4: convT GEMM + fused residual scatter (fp32). grid (8 nt, 8 jt, B)
// ---------------------------------------------------------------------------
__global__ __launch_bounds__(256) void up_kernel(const float* __restrict__ xin,
                                                 const float* __restrict__ upb,
                                                 float* __restrict__ out) {
    GEMM_PREAMBLE();
    int nt = blockIdx.x, jt = blockIdx.y, b = blockIdx.z;
    int n0 = nt * BM, j0 = jt * BN;
    const __half* A = g_o1 + (size_t)b * NTOK * KD + (size_t)n0 * KD;
    const __half* Bw = g_upwt + (size_t)j0 * KD;

#define UP_STAGE(bi, s)                                                        \
    do {                                                                       \
        stage_rows_h(Abuf[bi], A + (s) * 32, KD, tid);                         \
        stage_rows_h(Bbuf[bi], Bw + (s) * 32, KD, tid);                        \
    } while (0)

    PIPE_LOOP(8, UP_STAGE);

    float* Cs = (float*)smh;                       // 128*130 floats
#pragma unroll
    for (int mf = 0; mf < 4; mf++)
#pragma unroll
        for (int nf = 0; nf < 4; nf++) {
            int rl = m_off + mf * 16 + qid;
            int cl = n_off + nf * 8 + 2 * tig;
            *(float2*)&Cs[rl * 130 + cl] = make_float2(acc[mf][nf][0], acc[mf][nf][1]);
            *(float2*)&Cs[(rl + 8) * 130 + cl] = make_float2(acc[mf][nf][2], acc[mf][nf][3]);
        }
    __syncthreads();

#pragma unroll
    for (int it = 0; it < 64; it++) {
        int e = it * 256 + tid;
        int c   = e & 63;
        int r_l = (e >> 6) & 7;
        int o_l = e >> 9;
        int jl = o_l * 4 + (r_l & 1) * 2 + (c & 1);
        int nl = (r_l >> 1) * 32 + (c >> 1);
        int o = jt * 32 + o_l;
        size_t gi = (((size_t)b * CIN + o) * SIDE + nt * 8 + r_l) * SIDE + c;
        out[gi] = xin[gi] + upb[o] + Cs[nl * 130 + jl];
    }
}

// ---------------------------------------------------------------------------
// Launch
// ---------------------------------------------------------------------------
extern "C" void kernel_launch(void* const* d_in, const int* in_sizes, int n_in,
                              void* d_out, int out_size) {
    const float* x   = (const float*)d_in[0];
    const float* q_w = (const float*)d_in[1];
    const float* q_b = (const float*)d_in[2];
    const float* k_w = (const float*)d_in[3];
    const float* k_b = (const float*)d_in[4];
    const float* v_w = (const float*)d_in[5];
    const float* v_b = (const float*)d_in[6];
    const float* up_w = (const float*)d_in[7];
    const float* up_b = (const float*)d_in[8];
    float* out = (float*)d_out;

    static bool attr_done = false;
    if (!attr_done) {
        cudaFuncSetAttribute(proj_kernel,  cudaFuncAttributeMaxDynamicSharedMemorySize, SMEM_BYTES);
        cudaFuncSetAttribute(score_kernel, cudaFuncAttributeMaxDynamicSharedMemorySize, SMEM_BYTES);
        cudaFuncSetAttribute(av_kernel,    cudaFuncAttributeMaxDynamicSharedMemorySize, SMEM_BYTES);
        cudaFuncSetAttribute(up_kernel,    cudaFuncAttributeMaxDynamicSharedMemorySize, SMEM_BYTES);
        attr_done = true;
    }

    long long xp_total = (long long)BATCH * CIN * XPC;
    xpad_kernel<<<(unsigned)((xp_total + 255) / 256), 256>>>(x);
    pb_kernel<<<3 * NTOK * KD / 256, 256>>>(q_w, q_b, k_w, k_b, v_w, v_b);
    wt_kernel<<<3 * 256 * 1024 / 256, 256>>>(q_w, k_w, v_w);
    upwt_kernel<<<1024 * KD / 256, 256>>>(up_w);
    proj_kernel<<<dim3(8, 2, BATCH * 3), 256, SMEM_BYTES>>>();
    vt_kernel<<<dim3(32, 8, BATCH), dim3(32, 8)>>>();
    score_kernel<<<dim3(8, 8, BATCH), 256, SMEM_BYTES>>>();
    softmax_kernel<<<BATCH * NTOK, 128>>>();
    av_kernel<<<dim3(8, 2, BATCH), 256, SMEM_BYTES>>>();
    up_kernel<<<dim3(8, 8, BATCH), 256, SMEM_BYTES>>>(x, up_b, out);
}